// round 1
// baseline (speedup 1.0000x reference)
#include <cuda_runtime.h>
#include <cuda_bf16.h>

#define TWO_N   8192
#define N_HALF  4096
#define D       256
#define TAU_INV 10.0f

#define BM 128
#define BN 128
#define BK 32
#define SA_STRIDE 132          // padded, 16B-aligned rows, bank-spread
#define NCHUNK 8
#define COLS_PER_CHUNK (TWO_N / NCHUNK)   // 1024

// Scratch (no allocations allowed): normalized z, per-chunk row partials, pos dots.
__device__ float g_Z[TWO_N * D];
__device__ float g_partial[NCHUNK * TWO_N];
__device__ float g_pos[TWO_N];

// ---------------------------------------------------------------------------
// Kernel 1: L2-normalize rows of x1,x2 into g_Z (concatenated).
// One block per row, 256 threads = D.
// ---------------------------------------------------------------------------
__global__ void normalize_kernel(const float* __restrict__ x1,
                                 const float* __restrict__ x2) {
    int row = blockIdx.x;
    int tid = threadIdx.x;
    const float* src = (row < N_HALF) ? (x1 + (size_t)row * D)
                                      : (x2 + (size_t)(row - N_HALF) * D);
    float v = src[tid];
    float ss = v * v;
    #pragma unroll
    for (int o = 16; o > 0; o >>= 1) ss += __shfl_xor_sync(0xffffffffu, ss, o);
    __shared__ float wsum[8];
    if ((tid & 31) == 0) wsum[tid >> 5] = ss;
    __syncthreads();
    float tot = 0.f;
    #pragma unroll
    for (int w = 0; w < 8; ++w) tot += wsum[w];
    float nrm = sqrtf(tot);
    float dn = fmaxf(nrm, 1e-12f);
    g_Z[(size_t)row * D + tid] = v / dn;
}

// ---------------------------------------------------------------------------
// Kernel 2: fused sim-tile GEMM + exp + row-sum.
// Block = 128 rows x (1024-column chunk, 8 tiles of 128).
// 256 threads, 8x8 per-thread microtile, BK=32 smem staging.
// ---------------------------------------------------------------------------
__global__ __launch_bounds__(256, 2)
void sim_rowsum_kernel() {
    // As/Bs overlap with the reduction buffer (used strictly after the k-loops).
    __shared__ float smem[2 * BK * SA_STRIDE];   // 33.8 KB
    float* As = smem;                            // [BK][SA_STRIDE]
    float* Bs = smem + BK * SA_STRIDE;

    const int tid = threadIdx.x;
    const int tx = tid & 15;          // 0..15  (column group)
    const int ty = tid >> 4;          // 0..15  (row group)
    const int rowBase = blockIdx.y * BM;
    const int colChunk = blockIdx.x;

    const int lm  = tid >> 3;         // 0..31  loader: row within 32-row group
    const int lk4 = tid & 7;          // 0..7   loader: float4 index along k

    float rowAcc[8];
    #pragma unroll
    for (int i = 0; i < 8; ++i) rowAcc[i] = 0.f;

    for (int t = 0; t < COLS_PER_CHUNK / BN; ++t) {
        const int colBase = colChunk * COLS_PER_CHUNK + t * BN;

        float acc[8][8];
        #pragma unroll
        for (int i = 0; i < 8; ++i)
            #pragma unroll
            for (int j = 0; j < 8; ++j) acc[i][j] = 0.f;

        for (int kb = 0; kb < D; kb += BK) {
            // Stage A (rows rowBase..+128) and B (rows colBase..+128), k = kb..kb+32,
            // transposed into smem as [k][m] for vectorized compute reads.
            #pragma unroll
            for (int rr = 0; rr < 4; ++rr) {
                int m = lm + rr * 32;
                float4 av = *(const float4*)&g_Z[(size_t)(rowBase + m) * D + kb + lk4 * 4];
                As[(lk4 * 4 + 0) * SA_STRIDE + m] = av.x;
                As[(lk4 * 4 + 1) * SA_STRIDE + m] = av.y;
                As[(lk4 * 4 + 2) * SA_STRIDE + m] = av.z;
                As[(lk4 * 4 + 3) * SA_STRIDE + m] = av.w;
                float4 bv = *(const float4*)&g_Z[(size_t)(colBase + m) * D + kb + lk4 * 4];
                Bs[(lk4 * 4 + 0) * SA_STRIDE + m] = bv.x;
                Bs[(lk4 * 4 + 1) * SA_STRIDE + m] = bv.y;
                Bs[(lk4 * 4 + 2) * SA_STRIDE + m] = bv.z;
                Bs[(lk4 * 4 + 3) * SA_STRIDE + m] = bv.w;
            }
            __syncthreads();

            #pragma unroll
            for (int kk = 0; kk < BK; ++kk) {
                float a[8], b[8];
                *(float4*)&a[0] = *(const float4*)&As[kk * SA_STRIDE + ty * 8];
                *(float4*)&a[4] = *(const float4*)&As[kk * SA_STRIDE + ty * 8 + 4];
                *(float4*)&b[0] = *(const float4*)&Bs[kk * SA_STRIDE + tx * 8];
                *(float4*)&b[4] = *(const float4*)&Bs[kk * SA_STRIDE + tx * 8 + 4];
                #pragma unroll
                for (int i = 0; i < 8; ++i)
                    #pragma unroll
                    for (int j = 0; j < 8; ++j)
                        acc[i][j] += a[i] * b[j];
            }
            __syncthreads();
        }

        // Epilogue: exp + accumulate, handle diagonal (=> +1) and pos capture.
        #pragma unroll
        for (int i = 0; i < 8; ++i) {
            int r = rowBase + ty * 8 + i;
            int posCol = (r + N_HALF) & (TWO_N - 1);
            #pragma unroll
            for (int j = 0; j < 8; ++j) {
                int c = colBase + tx * 8 + j;
                float s = acc[i][j];
                if (c == posCol) g_pos[r] = s;      // exactly one writer per row
                float e = (c == r) ? 1.0f : __expf(s * TAU_INV);
                rowAcc[i] += e;
            }
        }
    }

    // Deterministic block reduction of rowAcc across the 16 tx groups.
    __syncthreads();                   // done with As/Bs; alias as red[128][17]
    float* red = smem;                 // needs 128*17 = 2176 floats (fits)
    #pragma unroll
    for (int i = 0; i < 8; ++i)
        red[(ty * 8 + i) * 17 + tx] = rowAcc[i];
    __syncthreads();

    if (tid < BM) {
        float s = 0.f;
        #pragma unroll
        for (int x = 0; x < 16; ++x) s += red[tid * 17 + x];
        g_partial[colChunk * TWO_N + rowBase + tid] = s;
    }
}

// ---------------------------------------------------------------------------
// Kernel 3: combine partials, per-row loss, deterministic reduce to scalar.
// ---------------------------------------------------------------------------
__global__ void finalize_kernel(float* __restrict__ out) {
    int tid = threadIdx.x;   // 1024
    float local = 0.f;
    for (int r = tid; r < TWO_N; r += 1024) {
        float denom = 0.f;
        #pragma unroll
        for (int c = 0; c < NCHUNK; ++c) denom += g_partial[c * TWO_N + r];
        local += logf(denom) - g_pos[r] * TAU_INV;
    }
    #pragma unroll
    for (int o = 16; o > 0; o >>= 1) local += __shfl_xor_sync(0xffffffffu, local, o);
    __shared__ float wsum[32];
    if ((tid & 31) == 0) wsum[tid >> 5] = local;
    __syncthreads();
    if (tid < 32) {
        float v = wsum[tid];
        #pragma unroll
        for (int o = 16; o > 0; o >>= 1) v += __shfl_xor_sync(0xffffffffu, v, o);
        if (tid == 0) out[0] = v / (float)TWO_N;
    }
}

// ---------------------------------------------------------------------------
extern "C" void kernel_launch(void* const* d_in, const int* in_sizes, int n_in,
                              void* d_out, int out_size) {
    const float* x1 = (const float*)d_in[0];
    const float* x2 = (const float*)d_in[1];
    float* out = (float*)d_out;
    (void)in_sizes; (void)n_in; (void)out_size;

    normalize_kernel<<<TWO_N, 256>>>(x1, x2);
    sim_rowsum_kernel<<<dim3(NCHUNK, TWO_N / BM), 256>>>();
    finalize_kernel<<<1, 1024>>>(out);
}

// round 4
// speedup vs baseline: 7.2777x; 7.2777x over previous
#include <cuda_runtime.h>
#include <cuda_bf16.h>
#include <cstdint>

#define TWO_N   8192
#define N_HALF  4096
#define D       256
#define TAU_INV 10.0f
#define LOG2E10 14.426950408889634f   // 10 / ln(2)

#define STRIDE  264                   // padded smem row: 264 bf16 = 528 B
#define SROW    528

// ---------------------------------------------------------------------------
// Scratch (allocations forbidden)
// ---------------------------------------------------------------------------
__device__ __nv_bfloat16 g_Zbf[TWO_N * D];   // normalized z, bf16
__device__ float g_partial[32 * TWO_N];      // (chunk*4 + wn) x row denominator partials
__device__ float g_rowblock[1024];           // per-block loss sums

__device__ __forceinline__ uint32_t smem_u32(const void* p) {
    uint32_t a;
    asm("{ .reg .u64 t; cvta.to.shared.u64 t, %1; cvt.u32.u64 %0, t; }" : "=r"(a) : "l"(p));
    return a;
}
__device__ __forceinline__ void cp16(uint32_t saddr, const void* g) {
    asm volatile("cp.async.cg.shared.global [%0], [%1], 16;" :: "r"(saddr), "l"(g));
}
#define CP_COMMIT() asm volatile("cp.async.commit_group;" ::: "memory")
#define CP_WAIT0()  asm volatile("cp.async.wait_group 0;" ::: "memory")

__device__ __forceinline__ void ldsm4(uint32_t* r, uint32_t addr) {
    asm volatile("ldmatrix.sync.aligned.m8n8.x4.shared.b16 {%0,%1,%2,%3}, [%4];"
                 : "=r"(r[0]), "=r"(r[1]), "=r"(r[2]), "=r"(r[3]) : "r"(addr));
}
__device__ __forceinline__ void mma16816(float* c, const uint32_t* a, const uint32_t* b) {
    asm volatile("mma.sync.aligned.m16n8k16.row.col.f32.bf16.bf16.f32 "
                 "{%0,%1,%2,%3}, {%4,%5,%6,%7}, {%8,%9}, {%0,%1,%2,%3};"
                 : "+f"(c[0]), "+f"(c[1]), "+f"(c[2]), "+f"(c[3])
                 : "r"(a[0]), "r"(a[1]), "r"(a[2]), "r"(a[3]), "r"(b[0]), "r"(b[1]));
}
__device__ __forceinline__ float exp10x(float s) {
    float e;
    asm("ex2.approx.f32 %0, %1;" : "=f"(e) : "f"(s * LOG2E10));
    return e;
}

// ---------------------------------------------------------------------------
// Kernel 1: L2-normalize rows into bf16. One warp per row.
// ---------------------------------------------------------------------------
__global__ void normalize_kernel(const float* __restrict__ x1, const float* __restrict__ x2) {
    int gw = (blockIdx.x * blockDim.x + threadIdx.x) >> 5;
    int lane = threadIdx.x & 31;
    if (gw >= TWO_N) return;
    const float4* src = (const float4*)((gw < N_HALF) ? (x1 + (size_t)gw * D)
                                                      : (x2 + (size_t)(gw - N_HALF) * D));
    float4 a = src[lane];
    float4 b = src[lane + 32];
    float ss = a.x*a.x + a.y*a.y + a.z*a.z + a.w*a.w
             + b.x*b.x + b.y*b.y + b.z*b.z + b.w*b.w;
    #pragma unroll
    for (int o = 16; o > 0; o >>= 1) ss += __shfl_xor_sync(0xffffffffu, ss, o);
    float inv = 1.0f / fmaxf(sqrtf(ss), 1e-12f);
    __nv_bfloat162 p0 = __floats2bfloat162_rn(a.x * inv, a.y * inv);
    __nv_bfloat162 p1 = __floats2bfloat162_rn(a.z * inv, a.w * inv);
    __nv_bfloat162 p2 = __floats2bfloat162_rn(b.x * inv, b.y * inv);
    __nv_bfloat162 p3 = __floats2bfloat162_rn(b.z * inv, b.w * inv);
    uint2 u0, u1;
    u0.x = *reinterpret_cast<uint32_t*>(&p0); u0.y = *reinterpret_cast<uint32_t*>(&p1);
    u1.x = *reinterpret_cast<uint32_t*>(&p2); u1.y = *reinterpret_cast<uint32_t*>(&p3);
    uint2* dst = (uint2*)(g_Zbf + (size_t)gw * D);
    dst[lane] = u0;
    dst[lane + 32] = u1;
}

// ---------------------------------------------------------------------------
// Kernel 2: HMMA bf16 GEMM + fused exp/rowsum epilogue.
// Grid (8 col-chunks, 64 row-tiles), 256 threads = 8 warps (warp tile 64x32).
// smem: A tile 128x264bf16 + B double buffer, padded rows (conflict-free LDSM).
// ---------------------------------------------------------------------------
#define SMEM_A   0
#define SMEM_B0  (128 * SROW)
#define SMEM_B1  (SMEM_B0 + 128 * SROW)
#define SMEM_TOT (SMEM_B1 + 128 * SROW)     // 202752 B

__device__ __forceinline__ void load_tile(uint32_t stile, int gRowBase, int tid) {
    const uint4* src = ((const uint4*)g_Zbf) + (size_t)gRowBase * 32;   // 32 x 16B per row
    #pragma unroll
    for (int it = 0; it < 16; ++it) {
        int idx = it * 256 + tid;
        int row = idx >> 5, c16 = idx & 31;
        cp16(stile + (uint32_t)(row * SROW + c16 * 16), src + (size_t)row * 32 + c16);
    }
}

__global__ __launch_bounds__(256, 1) void sim_kernel() {
    extern __shared__ char smem[];
    const uint32_t sbase = smem_u32(smem);
    const uint32_t sA = sbase + SMEM_A;
    const uint32_t sB0 = sbase + SMEM_B0;
    const uint32_t sB1 = sbase + SMEM_B1;

    const int tid = threadIdx.x;
    const int lane = tid & 31, wid = tid >> 5;
    const int wm = wid & 1;                  // m half (64 rows)
    const int wn = wid >> 1;                 // n quarter (32 cols)
    const int rowBase = blockIdx.y * 128;
    const int chunk = blockIdx.x;
    const int colChunkBase = chunk * 1024;

    load_tile(sA, rowBase, tid);
    load_tile(sB0, colChunkBase, tid);
    CP_COMMIT();

    // ldmatrix per-lane address bases
    const uint32_t aBase = sA + (uint32_t)((wm * 64 + (lane & 15)) * SROW + (lane >> 4) * 16);
    const int bgrp = lane >> 3;
    const int b_n = ((bgrp & 2) ? 8 : 0) + (lane & 7);
    const int b_k = (bgrp & 1) * 8;
    const uint32_t bOff = (uint32_t)((wn * 32 + b_n) * SROW + b_k * 2);

    float acc[8];
    #pragma unroll
    for (int i = 0; i < 8; ++i) acc[i] = 0.0f;

    CP_WAIT0();
    __syncthreads();

    #pragma unroll 1
    for (int t = 0; t < 8; ++t) {
        if (t < 7) {   // prefetch next B into the buffer last read in iter t-1
            load_tile(((t + 1) & 1) ? sB1 : sB0, colChunkBase + (t + 1) * 128, tid);
            CP_COMMIT();
        }
        const uint32_t sB = ((t & 1) ? sB1 : sB0) + bOff;

        float c[4][4][4];
        #pragma unroll
        for (int mf = 0; mf < 4; ++mf)
            #pragma unroll
            for (int nf = 0; nf < 4; ++nf)
                #pragma unroll
                for (int q = 0; q < 4; ++q) c[mf][nf][q] = 0.0f;

        #pragma unroll
        for (int kb = 0; kb < 16; ++kb) {
            uint32_t af[4][4], bf[4][2];
            #pragma unroll
            for (int mf = 0; mf < 4; ++mf)
                ldsm4(af[mf], aBase + (uint32_t)(mf * 16 * SROW + kb * 32));
            #pragma unroll
            for (int h = 0; h < 2; ++h) {
                uint32_t r4[4];
                ldsm4(r4, sB + (uint32_t)(h * 16 * SROW + kb * 32));
                bf[h*2][0] = r4[0]; bf[h*2][1] = r4[1];
                bf[h*2+1][0] = r4[2]; bf[h*2+1][1] = r4[3];
            }
            #pragma unroll
            for (int mf = 0; mf < 4; ++mf)
                #pragma unroll
                for (int nf = 0; nf < 4; ++nf)
                    mma16816(c[mf][nf], af[mf], bf[nf]);
        }

        // Epilogue: exp + accumulate (diag/pos corrected later in row_loss)
        #pragma unroll
        for (int mf = 0; mf < 4; ++mf)
            #pragma unroll
            for (int nf = 0; nf < 4; ++nf) {
                acc[mf*2+0] += exp10x(c[mf][nf][0]) + exp10x(c[mf][nf][1]);
                acc[mf*2+1] += exp10x(c[mf][nf][2]) + exp10x(c[mf][nf][3]);
            }

        if (t < 7) { CP_WAIT0(); __syncthreads(); }
    }

    // Reduce across the 4 lanes sharing each row (lane%4 varies over cols)
    #pragma unroll
    for (int i = 0; i < 8; ++i) {
        acc[i] += __shfl_xor_sync(0xffffffffu, acc[i], 1);
        acc[i] += __shfl_xor_sync(0xffffffffu, acc[i], 2);
    }
    if ((lane & 3) == 0) {
        int rbase = rowBase + wm * 64 + (lane >> 2);
        #pragma unroll
        for (int i = 0; i < 8; ++i) {
            int r = rbase + (i >> 1) * 16 + (i & 1) * 8;
            g_partial[(size_t)(chunk * 4 + wn) * TWO_N + r] = acc[i];
        }
    }
}

// ---------------------------------------------------------------------------
// Kernel 3: per-row loss. One warp per row: recompute self-dot & pos-dot from
// bf16 z in fp32, correct diagonal, combine 32 partials.
// ---------------------------------------------------------------------------
__global__ void row_loss_kernel() {
    int tid = threadIdx.x;           // 256
    int lane = tid & 31, w = tid >> 5;
    int r = blockIdx.x * 8 + w;
    int p = (r + N_HALF) & (TWO_N - 1);
    const uint4* zr = (const uint4*)(g_Zbf + (size_t)r * D);
    const uint4* zp = (const uint4*)(g_Zbf + (size_t)p * D);
    uint4 ur = zr[lane], up = zp[lane];

    float self = 0.f, pos = 0.f;
    const uint32_t* pr = (const uint32_t*)&ur;
    const uint32_t* pp = (const uint32_t*)&up;
    #pragma unroll
    for (int q = 0; q < 4; ++q) {
        __nv_bfloat162 br = *(const __nv_bfloat162*)&pr[q];
        __nv_bfloat162 bp = *(const __nv_bfloat162*)&pp[q];
        float r0 = __bfloat162float(br.x), r1 = __bfloat162float(br.y);
        float p0 = __bfloat162float(bp.x), p1 = __bfloat162float(bp.y);
        self += r0 * r0 + r1 * r1;
        pos  += r0 * p0 + r1 * p1;
    }
    #pragma unroll
    for (int o = 16; o > 0; o >>= 1) {
        self += __shfl_xor_sync(0xffffffffu, self, o);
        pos  += __shfl_xor_sync(0xffffffffu, pos, o);
    }

    __shared__ float ws[8];
    if (lane == 0) {
        float denom = 0.f;
        #pragma unroll
        for (int c = 0; c < 32; ++c) denom += g_partial[(size_t)c * TWO_N + r];
        denom = denom - exp10x(self) + 1.0f;     // diag: exp(0)=1, remove exp(10*s_rr)
        ws[w] = logf(denom) - pos * TAU_INV;
    }
    __syncthreads();
    if (tid == 0) {
        float s = 0.f;
        #pragma unroll
        for (int i = 0; i < 8; ++i) s += ws[i];
        g_rowblock[blockIdx.x] = s;
    }
}

__global__ void final_kernel(float* __restrict__ out) {
    int tid = threadIdx.x;           // 256
    float v = g_rowblock[tid] + g_rowblock[tid + 256] + g_rowblock[tid + 512] + g_rowblock[tid + 768];
    #pragma unroll
    for (int o = 16; o > 0; o >>= 1) v += __shfl_xor_sync(0xffffffffu, v, o);
    __shared__ float ws[8];
    if ((tid & 31) == 0) ws[tid >> 5] = v;
    __syncthreads();
    if (tid == 0) {
        float s = 0.f;
        #pragma unroll
        for (int i = 0; i < 8; ++i) s += ws[i];
        out[0] = s / (float)TWO_N;
    }
}

// ---------------------------------------------------------------------------
extern "C" void kernel_launch(void* const* d_in, const int* in_sizes, int n_in,
                              void* d_out, int out_size) {
    const float* x1 = (const float*)d_in[0];
    const float* x2 = (const float*)d_in[1];
    float* out = (float*)d_out;
    (void)in_sizes; (void)n_in; (void)out_size;

    cudaFuncSetAttribute(sim_kernel, cudaFuncAttributeMaxDynamicSharedMemorySize, SMEM_TOT);

    normalize_kernel<<<TWO_N / 8, 256>>>(x1, x2);
    sim_kernel<<<dim3(8, 64), 256, SMEM_TOT>>>();
    row_loss_kernel<<<1024, 256>>>();
    final_kernel<<<1, 256>>>(out);
}

// round 10
// speedup vs baseline: 7.6821x; 1.0556x over previous
#include <cuda_runtime.h>
#include <cuda_bf16.h>
#include <cstdint>

#define TWO_N   8192
#define N_HALF  4096
#define D       256
#define TAU_INV 10.0f
#define LOG2E10 14.426950408889634f   // 10 / ln(2)

#define SROW    528                   // padded smem row bytes (264 bf16)

// ---------------------------------------------------------------------------
// Scratch (allocations forbidden)
// ---------------------------------------------------------------------------
__device__ __nv_bfloat16 g_Zbf[TWO_N * D];   // normalized z, bf16
__device__ float g_partial[64 * TWO_N];      // (chunk*4 + wn) x row denominator partials
__device__ float g_rowblock[1024];           // per-block loss sums
__device__ int   g_count = 0;                // last-block arrival counter

__device__ __forceinline__ uint32_t smem_u32(const void* p) {
    uint32_t a;
    asm("{ .reg .u64 t; cvta.to.shared.u64 t, %1; cvt.u32.u64 %0, t; }" : "=r"(a) : "l"(p));
    return a;
}
__device__ __forceinline__ void cp16(uint32_t saddr, const void* g) {
    asm volatile("cp.async.cg.shared.global [%0], [%1], 16;" :: "r"(saddr), "l"(g));
}
#define CP_COMMIT() asm volatile("cp.async.commit_group;" ::: "memory")
#define CP_WAIT0()  asm volatile("cp.async.wait_group 0;" ::: "memory")

__device__ __forceinline__ void ldsm4(uint32_t* r, uint32_t addr) {
    asm volatile("ldmatrix.sync.aligned.m8n8.x4.shared.b16 {%0,%1,%2,%3}, [%4];"
                 : "=r"(r[0]), "=r"(r[1]), "=r"(r[2]), "=r"(r[3]) : "r"(addr));
}
__device__ __forceinline__ void mma16816(float* c, const uint32_t* a, const uint32_t* b) {
    asm volatile("mma.sync.aligned.m16n8k16.row.col.f32.bf16.bf16.f32 "
                 "{%0,%1,%2,%3}, {%4,%5,%6,%7}, {%8,%9}, {%0,%1,%2,%3};"
                 : "+f"(c[0]), "+f"(c[1]), "+f"(c[2]), "+f"(c[3])
                 : "r"(a[0]), "r"(a[1]), "r"(a[2]), "r"(a[3]), "r"(b[0]), "r"(b[1]));
}
__device__ __forceinline__ float exp10x(float s) {
    float e;
    asm("ex2.approx.f32 %0, %1;" : "=f"(e) : "f"(s * LOG2E10));
    return e;
}

// ---------------------------------------------------------------------------
// Kernel 1: L2-normalize rows into bf16. One warp per row.
// ---------------------------------------------------------------------------
__global__ void normalize_kernel(const float* __restrict__ x1, const float* __restrict__ x2) {
    int gw = (blockIdx.x * blockDim.x + threadIdx.x) >> 5;
    int lane = threadIdx.x & 31;
    if (gw >= TWO_N) return;
    const float4* src = (const float4*)((gw < N_HALF) ? (x1 + (size_t)gw * D)
                                                      : (x2 + (size_t)(gw - N_HALF) * D));
    float4 a = src[lane];
    float4 b = src[lane + 32];
    float ss = a.x*a.x + a.y*a.y + a.z*a.z + a.w*a.w
             + b.x*b.x + b.y*b.y + b.z*b.z + b.w*b.w;
    #pragma unroll
    for (int o = 16; o > 0; o >>= 1) ss += __shfl_xor_sync(0xffffffffu, ss, o);
    float inv = 1.0f / fmaxf(sqrtf(ss), 1e-12f);
    __nv_bfloat162 p0 = __floats2bfloat162_rn(a.x * inv, a.y * inv);
    __nv_bfloat162 p1 = __floats2bfloat162_rn(a.z * inv, a.w * inv);
    __nv_bfloat162 p2 = __floats2bfloat162_rn(b.x * inv, b.y * inv);
    __nv_bfloat162 p3 = __floats2bfloat162_rn(b.z * inv, b.w * inv);
    uint2 u0, u1;
    u0.x = *reinterpret_cast<uint32_t*>(&p0); u0.y = *reinterpret_cast<uint32_t*>(&p1);
    u1.x = *reinterpret_cast<uint32_t*>(&p2); u1.y = *reinterpret_cast<uint32_t*>(&p3);
    uint2* dst = (uint2*)(g_Zbf + (size_t)gw * D);
    dst[lane] = u0;
    dst[lane + 32] = u1;
}

// ---------------------------------------------------------------------------
// Kernel 2: HMMA bf16 GEMM + fused exp/rowsum epilogue.
// Grid (16 col-chunks x 64 row-tiles) = 1024 CTAs (6.92 waves, ~1% tail).
// 512 threads = 16 warps, warp tile 32x32 (4 warps/SMSP for latency hiding).
// ---------------------------------------------------------------------------
#define SMEM_A   0
#define SMEM_B0  (128 * SROW)
#define SMEM_B1  (SMEM_B0 + 128 * SROW)
#define SMEM_TOT (SMEM_B1 + 128 * SROW)     // 202752 B

__device__ __forceinline__ void load_tile(uint32_t stile, int gRowBase, int tid) {
    const uint4* src = ((const uint4*)g_Zbf) + (size_t)gRowBase * 32;   // 32 x 16B per row
    #pragma unroll
    for (int it = 0; it < 8; ++it) {
        int idx = it * 512 + tid;
        int row = idx >> 5, c16 = idx & 31;
        cp16(stile + (uint32_t)(row * SROW + c16 * 16), src + (size_t)row * 32 + c16);
    }
}

__global__ __launch_bounds__(512, 1) void sim_kernel() {
    extern __shared__ char smem[];
    const uint32_t sbase = smem_u32(smem);
    const uint32_t sA = sbase + SMEM_A;
    const uint32_t sB0 = sbase + SMEM_B0;
    const uint32_t sB1 = sbase + SMEM_B1;

    const int tid = threadIdx.x;
    const int lane = tid & 31, wid = tid >> 5;
    const int wm = wid & 3;                  // m quarter (32 rows)
    const int wn = wid >> 2;                 // n quarter (32 cols)
    const int rowBase = blockIdx.y * 128;
    const int chunk = blockIdx.x;            // 0..15
    const int colChunkBase = chunk * 512;

    load_tile(sA, rowBase, tid);
    load_tile(sB0, colChunkBase, tid);
    CP_COMMIT();

    // ldmatrix per-lane address bases (same empirically-verified mapping as R4)
    const uint32_t aBase = sA + (uint32_t)((wm * 32 + (lane & 15)) * SROW + (lane >> 4) * 16);
    const int bgrp = lane >> 3;
    const int b_n = ((bgrp & 2) ? 8 : 0) + (lane & 7);
    const int b_k = (bgrp & 1) * 8;
    const uint32_t bOff = (uint32_t)((wn * 32 + b_n) * SROW + b_k * 2);

    float acc[4];
    #pragma unroll
    for (int i = 0; i < 4; ++i) acc[i] = 0.0f;

    CP_WAIT0();
    __syncthreads();

    #pragma unroll 1
    for (int t = 0; t < 4; ++t) {
        if (t < 3) {   // prefetch next B into the buffer last read in iter t-1
            load_tile(((t + 1) & 1) ? sB1 : sB0, colChunkBase + (t + 1) * 128, tid);
            CP_COMMIT();
        }
        const uint32_t sB = ((t & 1) ? sB1 : sB0) + bOff;

        float c[2][4][4];
        #pragma unroll
        for (int mf = 0; mf < 2; ++mf)
            #pragma unroll
            for (int nf = 0; nf < 4; ++nf)
                #pragma unroll
                for (int q = 0; q < 4; ++q) c[mf][nf][q] = 0.0f;

        #pragma unroll
        for (int kb = 0; kb < 16; ++kb) {
            uint32_t af[2][4], bf[4][2];
            #pragma unroll
            for (int mf = 0; mf < 2; ++mf)
                ldsm4(af[mf], aBase + (uint32_t)(mf * 16 * SROW + kb * 32));
            #pragma unroll
            for (int h = 0; h < 2; ++h) {
                uint32_t r4[4];
                ldsm4(r4, sB + (uint32_t)(h * 16 * SROW + kb * 32));
                bf[h*2][0] = r4[0]; bf[h*2][1] = r4[1];
                bf[h*2+1][0] = r4[2]; bf[h*2+1][1] = r4[3];
            }
            #pragma unroll
            for (int mf = 0; mf < 2; ++mf)
                #pragma unroll
                for (int nf = 0; nf < 4; ++nf)
                    mma16816(c[mf][nf], af[mf], bf[nf]);
        }

        // Epilogue: exp + accumulate (diag/pos corrected later in row_loss)
        #pragma unroll
        for (int mf = 0; mf < 2; ++mf)
            #pragma unroll
            for (int nf = 0; nf < 4; ++nf) {
                acc[mf*2+0] += exp10x(c[mf][nf][0]) + exp10x(c[mf][nf][1]);
                acc[mf*2+1] += exp10x(c[mf][nf][2]) + exp10x(c[mf][nf][3]);
            }

        if (t < 3) { CP_WAIT0(); __syncthreads(); }
    }

    // Reduce across the 4 lanes sharing each row (lane%4 varies over cols)
    #pragma unroll
    for (int i = 0; i < 4; ++i) {
        acc[i] += __shfl_xor_sync(0xffffffffu, acc[i], 1);
        acc[i] += __shfl_xor_sync(0xffffffffu, acc[i], 2);
    }
    if ((lane & 3) == 0) {
        int rbase = rowBase + wm * 32 + (lane >> 2);
        #pragma unroll
        for (int i = 0; i < 4; ++i) {
            int r = rbase + (i >> 1) * 16 + (i & 1) * 8;
            g_partial[(size_t)(chunk * 4 + wn) * TWO_N + r] = acc[i];
        }
    }
}

// ---------------------------------------------------------------------------
// Kernel 3: per-row loss (warp per row) + fused final reduction (last block).
// ---------------------------------------------------------------------------
__global__ void row_loss_kernel(float* __restrict__ out) {
    int tid = threadIdx.x;           // 256
    int lane = tid & 31, w = tid >> 5;
    int r = blockIdx.x * 8 + w;
    int p = (r + N_HALF) & (TWO_N - 1);
    const uint4* zr = (const uint4*)(g_Zbf + (size_t)r * D);
    const uint4* zp = (const uint4*)(g_Zbf + (size_t)p * D);
    uint4 ur = zr[lane], up = zp[lane];

    float self = 0.f, pos = 0.f;
    const uint32_t* pr = (const uint32_t*)&ur;
    const uint32_t* pp = (const uint32_t*)&up;
    #pragma unroll
    for (int q = 0; q < 4; ++q) {
        __nv_bfloat162 br = *(const __nv_bfloat162*)&pr[q];
        __nv_bfloat162 bp = *(const __nv_bfloat162*)&pp[q];
        float r0 = __bfloat162float(br.x), r1 = __bfloat162float(br.y);
        float p0 = __bfloat162float(bp.x), p1 = __bfloat162float(bp.y);
        self += r0 * r0 + r1 * r1;
        pos  += r0 * p0 + r1 * p1;
    }
    #pragma unroll
    for (int o = 16; o > 0; o >>= 1) {
        self += __shfl_xor_sync(0xffffffffu, self, o);
        pos  += __shfl_xor_sync(0xffffffffu, pos, o);
    }

    __shared__ float ws[8];
    if (lane == 0) {
        float denom = 0.f;
        #pragma unroll
        for (int c = 0; c < 64; ++c) denom += g_partial[(size_t)c * TWO_N + r];
        denom = denom - exp10x(self) + 1.0f;     // diag: exp(0)=1, remove exp(10*s_rr)
        ws[w] = logf(denom) - pos * TAU_INV;
    }
    __syncthreads();
    __shared__ bool is_last;
    if (tid == 0) {
        float s = 0.f;
        #pragma unroll
        for (int i = 0; i < 8; ++i) s += ws[i];
        g_rowblock[blockIdx.x] = s;
        __threadfence();
        int old = atomicAdd(&g_count, 1);
        is_last = (old == (int)gridDim.x - 1);
    }
    __syncthreads();

    if (is_last) {
        // Deterministic final reduction over the 1024 block sums.
        float v = g_rowblock[tid] + g_rowblock[tid + 256]
                + g_rowblock[tid + 512] + g_rowblock[tid + 768];
        #pragma unroll
        for (int o = 16; o > 0; o >>= 1) v += __shfl_xor_sync(0xffffffffu, v, o);
        __shared__ float fs[8];
        if (lane == 0) fs[w] = v;
        __syncthreads();
        if (tid == 0) {
            float s = 0.f;
            #pragma unroll
            for (int i = 0; i < 8; ++i) s += fs[i];
            out[0] = s / (float)TWO_N;
            g_count = 0;                         // reset for next graph replay
        }
    }
}

// ---------------------------------------------------------------------------
extern "C" void kernel_launch(void* const* d_in, const int* in_sizes, int n_in,
                              void* d_out, int out_size) {
    const float* x1 = (const float*)d_in[0];
    const float* x2 = (const float*)d_in[1];
    float* out = (float*)d_out;
    (void)in_sizes; (void)n_in; (void)out_size;

    cudaFuncSetAttribute(sim_kernel, cudaFuncAttributeMaxDynamicSharedMemorySize, SMEM_TOT);

    normalize_kernel<<<TWO_N / 8, 256>>>(x1, x2);
    sim_kernel<<<dim3(16, 64), 512, SMEM_TOT>>>();
    row_loss_kernel<<<1024, 256>>>(out);
}

// round 16
// speedup vs baseline: 10.7413x; 1.3982x over previous
#include <cuda_runtime.h>
#include <cuda_bf16.h>
#include <cstdint>

#define TWO_N   8192
#define N_HALF  4096
#define D       256
#define TAU_INV 10.0f
#define LOG2E10 14.426950408889634f   // 10 / ln(2)

#define SROW    528                   // padded smem row bytes (264 bf16)
#define NSLOT   256

// ---------------------------------------------------------------------------
// Scratch (allocations forbidden)
// ---------------------------------------------------------------------------
__device__ __nv_bfloat16 g_Zbf[TWO_N * D];       // normalized z, bf16
__device__ float g_partial[(size_t)TWO_N * NSLOT]; // [row][slot] denominator partials (8MB)
__device__ float g_rowblock[1024];               // per-block loss sums
__device__ int   g_count = 0;                    // last-block arrival counter

__device__ __forceinline__ uint32_t smem_u32(const void* p) {
    uint32_t a;
    asm("{ .reg .u64 t; cvta.to.shared.u64 t, %1; cvt.u32.u64 %0, t; }" : "=r"(a) : "l"(p));
    return a;
}
__device__ __forceinline__ void cp16(uint32_t saddr, const void* g) {
    asm volatile("cp.async.cg.shared.global [%0], [%1], 16;" :: "r"(saddr), "l"(g));
}
#define CP_COMMIT() asm volatile("cp.async.commit_group;" ::: "memory")
#define CP_WAIT0()  asm volatile("cp.async.wait_group 0;" ::: "memory")
#define CP_WAIT1()  asm volatile("cp.async.wait_group 1;" ::: "memory")

__device__ __forceinline__ void ldsm4(uint32_t* r, uint32_t addr) {
    asm volatile("ldmatrix.sync.aligned.m8n8.x4.shared.b16 {%0,%1,%2,%3}, [%4];"
                 : "=r"(r[0]), "=r"(r[1]), "=r"(r[2]), "=r"(r[3]) : "r"(addr));
}
__device__ __forceinline__ void mma16816(float* c, const uint32_t* a, const uint32_t* b) {
    asm volatile("mma.sync.aligned.m16n8k16.row.col.f32.bf16.bf16.f32 "
                 "{%0,%1,%2,%3}, {%4,%5,%6,%7}, {%8,%9}, {%0,%1,%2,%3};"
                 : "+f"(c[0]), "+f"(c[1]), "+f"(c[2]), "+f"(c[3])
                 : "r"(a[0]), "r"(a[1]), "r"(a[2]), "r"(a[3]), "r"(b[0]), "r"(b[1]));
}
__device__ __forceinline__ float exp10x(float s) {
    float e;
    asm("ex2.approx.f32 %0, %1;" : "=f"(e) : "f"(s * LOG2E10));
    return e;
}

// ---------------------------------------------------------------------------
// Kernel 1: L2-normalize rows into bf16. One warp per row.
// ---------------------------------------------------------------------------
__global__ void normalize_kernel(const float* __restrict__ x1, const float* __restrict__ x2) {
    int gw = (blockIdx.x * blockDim.x + threadIdx.x) >> 5;
    int lane = threadIdx.x & 31;
    if (gw >= TWO_N) return;
    const float4* src = (const float4*)((gw < N_HALF) ? (x1 + (size_t)gw * D)
                                                      : (x2 + (size_t)(gw - N_HALF) * D));
    float4 a = src[lane];
    float4 b = src[lane + 32];
    float ss = a.x*a.x + a.y*a.y + a.z*a.z + a.w*a.w
             + b.x*b.x + b.y*b.y + b.z*b.z + b.w*b.w;
    #pragma unroll
    for (int o = 16; o > 0; o >>= 1) ss += __shfl_xor_sync(0xffffffffu, ss, o);
    float inv = 1.0f / fmaxf(sqrtf(ss), 1e-12f);
    __nv_bfloat162 p0 = __floats2bfloat162_rn(a.x * inv, a.y * inv);
    __nv_bfloat162 p1 = __floats2bfloat162_rn(a.z * inv, a.w * inv);
    __nv_bfloat162 p2 = __floats2bfloat162_rn(b.x * inv, b.y * inv);
    __nv_bfloat162 p3 = __floats2bfloat162_rn(b.z * inv, b.w * inv);
    uint2 u0, u1;
    u0.x = *reinterpret_cast<uint32_t*>(&p0); u0.y = *reinterpret_cast<uint32_t*>(&p1);
    u1.x = *reinterpret_cast<uint32_t*>(&p2); u1.y = *reinterpret_cast<uint32_t*>(&p3);
    uint2* dst = (uint2*)(g_Zbf + (size_t)gw * D);
    dst[lane] = u0;
    dst[lane + 32] = u1;
}

// ---------------------------------------------------------------------------
// Kernel 2: HMMA bf16 GEMM over UPPER-TRIANGLE tiles only (symmetry: exp(sim)
// is symmetric, so each off-diagonal tile also supplies its mirror rows'
// partial sums via column reduction). 0.508x the HMMA work of the full GEMM.
// 1056 CTAs: each CTA = one rt, strip of up to 2 ct tiles. 512 threads.
// Slots: row-partials -> ct*4+wn ; col-partials -> rt*4+wm (rt<ct). For a row
// in tile t these cover slots [4t,256) and [0,4t): complete & collision-free.
// ---------------------------------------------------------------------------
#define SMEM_A   0
#define SMEM_B0  (128 * SROW)
#define SMEM_B1  (SMEM_B0 + 128 * SROW)
#define SMEM_TOT (SMEM_B1 + 128 * SROW)     // 202752 B

__device__ __forceinline__ void load_tile(uint32_t stile, int gRowBase, int tid) {
    const uint4* src = ((const uint4*)g_Zbf) + (size_t)gRowBase * 32;   // 32 x 16B per row
    #pragma unroll
    for (int it = 0; it < 8; ++it) {
        int idx = it * 512 + tid;
        int row = idx >> 5, c16 = idx & 31;
        cp16(stile + (uint32_t)(row * SROW + c16 * 16), src + (size_t)row * 32 + c16);
    }
}

__global__ __launch_bounds__(512, 1) void sim_kernel() {
    extern __shared__ char smem[];
    const uint32_t sbase = smem_u32(smem);
    const uint32_t sA = sbase + SMEM_A;
    const uint32_t sB0 = sbase + SMEM_B0;
    const uint32_t sB1 = sbase + SMEM_B1;

    const int tid = threadIdx.x;
    const int lane = tid & 31, wid = tid >> 5;
    const int wm = wid & 3;                  // m quarter (32 rows)
    const int wn = wid >> 2;                 // n quarter (32 cols)

    // Decode blockIdx.x -> (rt, ct0, ntiles): strips of 2 ct-tiles per rt.
    int k = blockIdx.x, rt = 0;
    while (true) {
        int ns = (65 - rt) >> 1;             // ceil((64-rt)/2)
        if (k < ns) break;
        k -= ns; ++rt;
    }
    const int ct0 = rt + 2 * k;
    const int ntiles = (ct0 + 1 < 64) ? 2 : 1;
    const int rowBase = rt * 128;

    load_tile(sA, rowBase, tid);
    load_tile(sB0, ct0 * 128, tid);
    CP_COMMIT();
    if (ntiles == 2) { load_tile(sB1, (ct0 + 1) * 128, tid); CP_COMMIT(); }

    // ldmatrix per-lane address bases (R4-validated mapping)
    const uint32_t aBase = sA + (uint32_t)((wm * 32 + (lane & 15)) * SROW + (lane >> 4) * 16);
    const int bgrp = lane >> 3;
    const int b_n = ((bgrp & 2) ? 8 : 0) + (lane & 7);
    const int b_k = (bgrp & 1) * 8;
    const uint32_t bOff = (uint32_t)((wn * 32 + b_n) * SROW + b_k * 2);

    #pragma unroll 1
    for (int t = 0; t < ntiles; ++t) {
        // Wait: tile 0 needs A+B0 (allow B1 outstanding); tile 1 needs all.
        if (t == 0) { if (ntiles == 2) { CP_WAIT1(); } else { CP_WAIT0(); } }
        else       { CP_WAIT0(); }
        __syncthreads();

        const int ct = ct0 + t;
        const uint32_t sB = ((t == 0) ? sB0 : sB1) + bOff;

        float c[2][4][4];
        #pragma unroll
        for (int mf = 0; mf < 2; ++mf)
            #pragma unroll
            for (int nf = 0; nf < 4; ++nf)
                #pragma unroll
                for (int q = 0; q < 4; ++q) c[mf][nf][q] = 0.0f;

        #pragma unroll
        for (int kb = 0; kb < 16; ++kb) {
            uint32_t af[2][4], bf[4][2];
            #pragma unroll
            for (int mf = 0; mf < 2; ++mf)
                ldsm4(af[mf], aBase + (uint32_t)(mf * 16 * SROW + kb * 32));
            #pragma unroll
            for (int h = 0; h < 2; ++h) {
                uint32_t r4[4];
                ldsm4(r4, sB + (uint32_t)(h * 16 * SROW + kb * 32));
                bf[h*2][0] = r4[0]; bf[h*2][1] = r4[1];
                bf[h*2+1][0] = r4[2]; bf[h*2+1][1] = r4[3];
            }
            #pragma unroll
            for (int mf = 0; mf < 2; ++mf)
                #pragma unroll
                for (int nf = 0; nf < 4; ++nf)
                    mma16816(c[mf][nf], af[mf], bf[nf]);
        }

        // ---- Epilogue: exp once, accumulate row sums AND column sums ----
        float rowAcc[4] = {0.f, 0.f, 0.f, 0.f};
        float colv[4][2];
        #pragma unroll
        for (int nf = 0; nf < 4; ++nf) { colv[nf][0] = 0.f; colv[nf][1] = 0.f; }

        #pragma unroll
        for (int mf = 0; mf < 2; ++mf)
            #pragma unroll
            for (int nf = 0; nf < 4; ++nf) {
                float e0 = exp10x(c[mf][nf][0]);
                float e1 = exp10x(c[mf][nf][1]);
                float e2 = exp10x(c[mf][nf][2]);
                float e3 = exp10x(c[mf][nf][3]);
                rowAcc[mf*2+0] += e0 + e1;    // row lane>>2 (+mf*16)
                rowAcc[mf*2+1] += e2 + e3;    // row lane>>2+8 (+mf*16)
                colv[nf][0]    += e0 + e2;    // col 2*(lane%4)
                colv[nf][1]    += e1 + e3;    // col 2*(lane%4)+1
            }

        // Row partials: reduce over the 4 lanes covering each row's columns.
        #pragma unroll
        for (int i = 0; i < 4; ++i) {
            rowAcc[i] += __shfl_xor_sync(0xffffffffu, rowAcc[i], 1);
            rowAcc[i] += __shfl_xor_sync(0xffffffffu, rowAcc[i], 2);
        }
        if ((lane & 3) == 0) {
            int rbase = rowBase + wm * 32 + (lane >> 2);
            #pragma unroll
            for (int i = 0; i < 4; ++i) {
                int r = rbase + (i >> 1) * 16 + (i & 1) * 8;
                g_partial[(size_t)r * NSLOT + ct * 4 + wn] = rowAcc[i];
            }
        }

        // Column partials (mirror rows) — off-diagonal tiles only.
        if (ct != rt) {
            #pragma unroll
            for (int nf = 0; nf < 4; ++nf)
                #pragma unroll
                for (int s = 0; s < 2; ++s) {
                    float v = colv[nf][s];
                    v += __shfl_xor_sync(0xffffffffu, v, 4);
                    v += __shfl_xor_sync(0xffffffffu, v, 8);
                    v += __shfl_xor_sync(0xffffffffu, v, 16);
                    colv[nf][s] = v;
                }
            if (lane < 4) {
                #pragma unroll
                for (int nf = 0; nf < 4; ++nf)
                    #pragma unroll
                    for (int s = 0; s < 2; ++s) {
                        int cIdx = ct * 128 + wn * 32 + nf * 8 + 2 * lane + s;
                        g_partial[(size_t)cIdx * NSLOT + rt * 4 + wm] = colv[nf][s];
                    }
            }
        }
    }
}

// ---------------------------------------------------------------------------
// Kernel 3: per-row loss (warp per row) + fused final reduction (last block).
// ---------------------------------------------------------------------------
__global__ void row_loss_kernel(float* __restrict__ out) {
    int tid = threadIdx.x;           // 256
    int lane = tid & 31, w = tid >> 5;
    int r = blockIdx.x * 8 + w;
    int p = (r + N_HALF) & (TWO_N - 1);
    const uint4* zr = (const uint4*)(g_Zbf + (size_t)r * D);
    const uint4* zp = (const uint4*)(g_Zbf + (size_t)p * D);
    uint4 ur = zr[lane], up = zp[lane];

    float self = 0.f, pos = 0.f;
    const uint32_t* pr = (const uint32_t*)&ur;
    const uint32_t* pp = (const uint32_t*)&up;
    #pragma unroll
    for (int q = 0; q < 4; ++q) {
        __nv_bfloat162 br = *(const __nv_bfloat162*)&pr[q];
        __nv_bfloat162 bp = *(const __nv_bfloat162*)&pp[q];
        float r0 = __bfloat162float(br.x), r1 = __bfloat162float(br.y);
        float p0 = __bfloat162float(bp.x), p1 = __bfloat162float(bp.y);
        self += r0 * r0 + r1 * r1;
        pos  += r0 * p0 + r1 * p1;
    }

    // Denominator: sum the 256 partial slots (coalesced per warp).
    const float* gp = g_partial + (size_t)r * NSLOT;
    float dsum = 0.f;
    #pragma unroll
    for (int i = 0; i < 8; ++i) dsum += gp[lane + i * 32];

    #pragma unroll
    for (int o = 16; o > 0; o >>= 1) {
        self += __shfl_xor_sync(0xffffffffu, self, o);
        pos  += __shfl_xor_sync(0xffffffffu, pos, o);
        dsum += __shfl_xor_sync(0xffffffffu, dsum, o);
    }

    __shared__ float ws[8];
    if (lane == 0) {
        float denom = dsum - exp10x(self) + 1.0f;   // diag: exp(0)=1, remove exp(10*s_rr)
        ws[w] = logf(denom) - pos * TAU_INV;
    }
    __syncthreads();
    __shared__ bool is_last;
    if (tid == 0) {
        float s = 0.f;
        #pragma unroll
        for (int i = 0; i < 8; ++i) s += ws[i];
        g_rowblock[blockIdx.x] = s;
        __threadfence();
        int old = atomicAdd(&g_count, 1);
        is_last = (old == (int)gridDim.x - 1);
    }
    __syncthreads();

    if (is_last) {
        float v = g_rowblock[tid] + g_rowblock[tid + 256]
                + g_rowblock[tid + 512] + g_rowblock[tid + 768];
        #pragma unroll
        for (int o = 16; o > 0; o >>= 1) v += __shfl_xor_sync(0xffffffffu, v, o);
        __shared__ float fs[8];
        if (lane == 0) fs[w] = v;
        __syncthreads();
        if (tid == 0) {
            float s = 0.f;
            #pragma unroll
            for (int i = 0; i < 8; ++i) s += fs[i];
            out[0] = s / (float)TWO_N;
            g_count = 0;                         // reset for next graph replay
        }
    }
}

// ---------------------------------------------------------------------------
extern "C" void kernel_launch(void* const* d_in, const int* in_sizes, int n_in,
                              void* d_out, int out_size) {
    const float* x1 = (const float*)d_in[0];
    const float* x2 = (const float*)d_in[1];
    float* out = (float*)d_out;
    (void)in_sizes; (void)n_in; (void)out_size;

    cudaFuncSetAttribute(sim_kernel, cudaFuncAttributeMaxDynamicSharedMemorySize, SMEM_TOT);

    normalize_kernel<<<TWO_N / 8, 256>>>(x1, x2);
    sim_kernel<<<1056, 512, SMEM_TOT>>>();
    row_loss_kernel<<<1024, 256>>>(out);
}